// round 7
// baseline (speedup 1.0000x reference)
#include <cuda_runtime.h>
#include <cuda_bf16.h>
#include <cooperative_groups.h>

namespace cg = cooperative_groups;

// Problem shape (fixed by the dataset)
#define B_DIM 16
#define S_DIM 2048
#define D_DIM 256
#define ROWS  (B_DIM * S_DIM)          // 32768
#define QUADS (ROWS / 4)               // 8192 row-quads
#define P_ASEM 0.6f
#define Q_ASEM 0.4f
#define MASK_FILL 1e-9f

// Scratch for projected scores (no cudaMalloc allowed)
__device__ float g_si[ROWS];  // si + bias folded in
__device__ float g_sj[ROWS];

__device__ __forceinline__ float sig_blend(float si, float sjv, int m, float a) {
    float z = si + sjv;
    float s = __fdividef(1.f, 1.f + __expf(-z));
    return m ? fmaf(P_ASEM, s, Q_ASEM * a) : MASK_FILL;
}

// ---------------------------------------------------------------------------
// Single persistent cooperative kernel.
//  Phase 1: grid-strided dual projections (4 rows per warp-iteration)
//  grid.sync()
//  Phase 2: grid-strided fused elementwise (4 rows per block-iteration,
//           R6 fuse body: shared column vectors, adj-skip for masked rows)
// ---------------------------------------------------------------------------
__global__ __launch_bounds__(256, 4)
void mono_kernel(const float*  __restrict__ x,
                 const float4* __restrict__ adj4,
                 const int*    __restrict__ mask,
                 const float*  __restrict__ W,
                 const float*  __restrict__ bias,
                 float4*       __restrict__ out4) {
    const unsigned tid  = threadIdx.x;
    const int      lane = tid & 31;

    // ---------------- Phase 1: projections ----------------
    {
        const int gwarp  = (int)((blockIdx.x * blockDim.x + tid) >> 5);
        const int nwarps = (int)((gridDim.x * blockDim.x) >> 5);

        const float4* Wi4 = reinterpret_cast<const float4*>(W);          // W[0:256]
        const float4* Wj4 = reinterpret_cast<const float4*>(W + D_DIM);  // W[256:512]
        const float4 wi0 = __ldg(&Wi4[lane]);
        const float4 wi1 = __ldg(&Wi4[lane + 32]);
        const float4 wj0 = __ldg(&Wj4[lane]);
        const float4 wj1 = __ldg(&Wj4[lane + 32]);
        const float  bv  = __ldg(bias);

        for (int q = gwarp; q < QUADS; q += nwarps) {
            const int row0 = q << 2;

            // all 8 x loads up front
            float4 xv[4][2];
#pragma unroll
            for (int r = 0; r < 4; ++r) {
                const float4* x4 = reinterpret_cast<const float4*>(x) +
                                   (long)(row0 + r) * (D_DIM / 4);
                xv[r][0] = x4[lane];
                xv[r][1] = x4[lane + 32];
            }

            float si[4], sj[4];
#pragma unroll
            for (int r = 0; r < 4; ++r) {
                float a = 0.f, b2 = 0.f;
                a = fmaf(xv[r][0].x, wi0.x, a); a = fmaf(xv[r][0].y, wi0.y, a);
                a = fmaf(xv[r][0].z, wi0.z, a); a = fmaf(xv[r][0].w, wi0.w, a);
                a = fmaf(xv[r][1].x, wi1.x, a); a = fmaf(xv[r][1].y, wi1.y, a);
                a = fmaf(xv[r][1].z, wi1.z, a); a = fmaf(xv[r][1].w, wi1.w, a);
                b2 = fmaf(xv[r][0].x, wj0.x, b2); b2 = fmaf(xv[r][0].y, wj0.y, b2);
                b2 = fmaf(xv[r][0].z, wj0.z, b2); b2 = fmaf(xv[r][0].w, wj0.w, b2);
                b2 = fmaf(xv[r][1].x, wj1.x, b2); b2 = fmaf(xv[r][1].y, wj1.y, b2);
                b2 = fmaf(xv[r][1].z, wj1.z, b2); b2 = fmaf(xv[r][1].w, wj1.w, b2);
                si[r] = a; sj[r] = b2;
            }

#pragma unroll
            for (int off = 16; off > 0; off >>= 1) {
#pragma unroll
                for (int r = 0; r < 4; ++r) {
                    si[r] += __shfl_down_sync(0xFFFFFFFFu, si[r], off);
                    sj[r] += __shfl_down_sync(0xFFFFFFFFu, sj[r], off);
                }
            }
            if (lane == 0) {
#pragma unroll
                for (int r = 0; r < 4; ++r) {
                    g_si[row0 + r] = si[r] + bv;
                    g_sj[row0 + r] = sj[r];
                }
            }
        }
    }

    // ---------------- grid-wide barrier ----------------
    cg::this_grid().sync();

    // ---------------- Phase 2: fused elementwise ----------------
    const float4* sj4 = reinterpret_cast<const float4*>(g_sj);
    const int4*   mj4 = reinterpret_cast<const int4*>(mask);

    for (unsigned q = blockIdx.x; q < QUADS; q += gridDim.x) {
        const unsigned row0  = q << 2;                     // 4 rows, same batch
        const unsigned base  = row0 << 9;                  // first float4 of quad
        const unsigned cbase = ((row0 >> 11) << 9) + tid;  // sj/mask col float4 idx

        int mi[4];
#pragma unroll
        for (int r = 0; r < 4; ++r) mi[r] = mask[row0 + r];

        // issue ALL adj loads for unmasked rows up front
        float4 aA[4], aB[4];
#pragma unroll
        for (int r = 0; r < 4; ++r) {
            if (mi[r]) {
                const unsigned o = base + (r << 9) + tid;
                aA[r] = __ldcs(&adj4[o]);
                aB[r] = __ldcs(&adj4[o + 256]);
            }
        }

        // column vectors: shared by all 4 rows
        const float4 sjA = __ldg(&sj4[cbase]);
        const float4 sjB = __ldg(&sj4[cbase + 256]);
        const int4   mA  = __ldg(&mj4[cbase]);
        const int4   mB  = __ldg(&mj4[cbase + 256]);

#pragma unroll
        for (int r = 0; r < 4; ++r) {
            const unsigned o = base + (r << 9) + tid;
            if (mi[r]) {
                const float si = g_si[row0 + r];
                float4 out;
                out.x = sig_blend(si, sjA.x, mA.x, aA[r].x);
                out.y = sig_blend(si, sjA.y, mA.y, aA[r].y);
                out.z = sig_blend(si, sjA.z, mA.z, aA[r].z);
                out.w = sig_blend(si, sjA.w, mA.w, aA[r].w);
                __stcs(&out4[o], out);

                out.x = sig_blend(si, sjB.x, mB.x, aB[r].x);
                out.y = sig_blend(si, sjB.y, mB.y, aB[r].y);
                out.z = sig_blend(si, sjB.z, mB.z, aB[r].z);
                out.w = sig_blend(si, sjB.w, mB.w, aB[r].w);
                __stcs(&out4[o + 256], out);
            } else {
                const float4 fill = make_float4(MASK_FILL, MASK_FILL, MASK_FILL, MASK_FILL);
                __stcs(&out4[o], fill);
                __stcs(&out4[o + 256], fill);
            }
        }
    }
}

// ---------------------------------------------------------------------------
// Launch — single cooperative kernel, grid sized to exactly fill the chip.
// Inputs (metadata order): 0:x [16,2048,256] f32, 1:adj [16,2048,2048] f32,
//                          2:mask [16,2048] i32, 3:W [1,512] f32, 4:b [1] f32
// Output: [16,2048,2048] f32
// ---------------------------------------------------------------------------
extern "C" void kernel_launch(void* const* d_in, const int* in_sizes, int n_in,
                              void* d_out, int out_size) {
    const float* x    = (const float*)d_in[0];
    const float4* adj = (const float4*)d_in[1];
    const int*   mask = (const int*)d_in[2];
    const float* W    = (const float*)d_in[3];
    const float* bias = (const float*)d_in[4];
    float4* out = (float4*)d_out;

    // exact one-wave cooperative grid (deterministic per device)
    int dev = 0;
    cudaGetDevice(&dev);
    int sms = 0;
    cudaDeviceGetAttribute(&sms, cudaDevAttrMultiProcessorCount, dev);
    int maxB = 0;
    cudaOccupancyMaxActiveBlocksPerMultiprocessor(&maxB, mono_kernel, 256, 0);
    if (maxB < 1) maxB = 1;
    unsigned grid = (unsigned)(sms * maxB);
    if (grid > QUADS) grid = QUADS;

    cudaLaunchConfig_t cfg = {};
    cfg.gridDim  = dim3(grid, 1, 1);
    cfg.blockDim = dim3(256, 1, 1);
    cfg.dynamicSmemBytes = 0;
    cfg.stream = 0;

    cudaLaunchAttribute attrs[1];
    attrs[0].id = cudaLaunchAttributeCooperative;
    attrs[0].val.cooperative = 1;
    cfg.attrs = attrs;
    cfg.numAttrs = 1;

    cudaLaunchKernelEx(&cfg, mono_kernel, x, adj, mask, W, bias, out);
}

// round 8
// speedup vs baseline: 1.3329x; 1.3329x over previous
#include <cuda_runtime.h>
#include <cuda_bf16.h>

// Problem shape (fixed by the dataset)
#define B_DIM 16
#define S_DIM 2048
#define D_DIM 256
#define ROWS  (B_DIM * S_DIM)          // 32768
#define QUADS (ROWS / 4)               // 8192 row-quads (= fuse grid)
#define P_ASEM 0.6f
#define Q_ASEM 0.4f
#define MASK_FILL 1e-9f

#define PROJK 256                      // blocks that carry proj work (wave-1 safe)
#define PROJ_ROWS_PER_BLOCK (ROWS / PROJK)   // 128 rows -> 16 rows/warp -> 4 quad iters

// Scratch (no cudaMalloc allowed)
__device__ float    g_si[ROWS];  // si + bias folded in
__device__ float    g_sj[ROWS];
__device__ unsigned g_done;      // proj completion counter (reset each launch)

__device__ __forceinline__ unsigned ld_acquire(const unsigned* p) {
    unsigned v;
    asm volatile("ld.acquire.gpu.u32 %0, [%1];" : "=r"(v) : "l"(p) : "memory");
    return v;
}

__device__ __forceinline__ float sig_blend(float si, float sjv, int m, float a) {
    float z = si + sjv;
    float s = __fdividef(1.f, 1.f + __expf(-z));
    return m ? fmaf(P_ASEM, s, Q_ASEM * a) : MASK_FILL;
}

// ---------------------------------------------------------------------------
// Kernel 0: reset the completion counter (determinism across graph replays).
// ---------------------------------------------------------------------------
__global__ void reset_kernel() { g_done = 0; }

// ---------------------------------------------------------------------------
// Kernel 1 (mono): 8192 blocks — same grid shape as the proven R6 fuse.
//   blocks 0..PROJK-1 : proj for 128 rows each, then signal.
//   all blocks        : spin until proj complete, then R6 fuse quad.
// ---------------------------------------------------------------------------
__global__ __launch_bounds__(256) void mono_kernel(const float*  __restrict__ x,
                                                   const float4* __restrict__ adj4,
                                                   const int*    __restrict__ mask,
                                                   const float*  __restrict__ W,
                                                   const float*  __restrict__ bias,
                                                   float4*       __restrict__ out4) {
    const unsigned tid  = threadIdx.x;
    const int      lane = tid & 31;

    // ---------------- proj phase (blocks 0..PROJK-1 only) ----------------
    if (blockIdx.x < PROJK) {
        const int warpInBlk = tid >> 5;                       // 0..7
        const int rowBase   = blockIdx.x * PROJ_ROWS_PER_BLOCK
                            + warpInBlk * (PROJ_ROWS_PER_BLOCK / 8);  // 16 rows/warp

        const float4* Wi4 = reinterpret_cast<const float4*>(W);          // W[0:256]
        const float4* Wj4 = reinterpret_cast<const float4*>(W + D_DIM);  // W[256:512]
        const float4 wi0 = __ldg(&Wi4[lane]);
        const float4 wi1 = __ldg(&Wi4[lane + 32]);
        const float4 wj0 = __ldg(&Wj4[lane]);
        const float4 wj1 = __ldg(&Wj4[lane + 32]);
        const float  bv  = __ldg(bias);

#pragma unroll
        for (int it = 0; it < 4; ++it) {                      // 4 x 4 rows = 16 rows
            const int row0 = rowBase + it * 4;

            float4 xv[4][2];
#pragma unroll
            for (int r = 0; r < 4; ++r) {
                const float4* x4 = reinterpret_cast<const float4*>(x) +
                                   (long)(row0 + r) * (D_DIM / 4);
                xv[r][0] = x4[lane];
                xv[r][1] = x4[lane + 32];
            }

            float si[4], sj[4];
#pragma unroll
            for (int r = 0; r < 4; ++r) {
                float a = 0.f, b2 = 0.f;
                a = fmaf(xv[r][0].x, wi0.x, a); a = fmaf(xv[r][0].y, wi0.y, a);
                a = fmaf(xv[r][0].z, wi0.z, a); a = fmaf(xv[r][0].w, wi0.w, a);
                a = fmaf(xv[r][1].x, wi1.x, a); a = fmaf(xv[r][1].y, wi1.y, a);
                a = fmaf(xv[r][1].z, wi1.z, a); a = fmaf(xv[r][1].w, wi1.w, a);
                b2 = fmaf(xv[r][0].x, wj0.x, b2); b2 = fmaf(xv[r][0].y, wj0.y, b2);
                b2 = fmaf(xv[r][0].z, wj0.z, b2); b2 = fmaf(xv[r][0].w, wj0.w, b2);
                b2 = fmaf(xv[r][1].x, wj1.x, b2); b2 = fmaf(xv[r][1].y, wj1.y, b2);
                b2 = fmaf(xv[r][1].z, wj1.z, b2); b2 = fmaf(xv[r][1].w, wj1.w, b2);
                si[r] = a; sj[r] = b2;
            }

#pragma unroll
            for (int off = 16; off > 0; off >>= 1) {
#pragma unroll
                for (int r = 0; r < 4; ++r) {
                    si[r] += __shfl_down_sync(0xFFFFFFFFu, si[r], off);
                    sj[r] += __shfl_down_sync(0xFFFFFFFFu, sj[r], off);
                }
            }
            if (lane == 0) {
#pragma unroll
                for (int r = 0; r < 4; ++r) {
                    g_si[row0 + r] = si[r] + bv;
                    g_sj[row0 + r] = sj[r];
                }
            }
        }

        __syncthreads();
        __threadfence();                       // make g_si/g_sj visible (release)
        if (tid == 0) atomicAdd(&g_done, 1u);
    }

    // ---------------- software barrier: wait for all proj blocks ----------------
    if (tid == 0) {
        while (ld_acquire(&g_done) < PROJK) __nanosleep(64);
    }
    __syncthreads();

    // ---------------- fuse phase (exact R6 body, quad = blockIdx) ----------------
    const unsigned q     = blockIdx.x;
    const unsigned row0  = q << 2;                     // 4 rows, same batch
    const unsigned base  = row0 << 9;                  // first float4 of quad
    const unsigned cbase = ((row0 >> 11) << 9) + tid;  // sj/mask col float4 idx

    int mi[4];
#pragma unroll
    for (int r = 0; r < 4; ++r) mi[r] = mask[row0 + r];

    // masked rows: issue fill stores FIRST (no load dependency)
    const float4 fill = make_float4(MASK_FILL, MASK_FILL, MASK_FILL, MASK_FILL);
#pragma unroll
    for (int r = 0; r < 4; ++r) {
        if (!mi[r]) {
            const unsigned o = base + (r << 9) + tid;
            __stcs(&out4[o], fill);
            __stcs(&out4[o + 256], fill);
        }
    }

    // issue ALL adj loads for unmasked rows up front
    float4 aA[4], aB[4];
#pragma unroll
    for (int r = 0; r < 4; ++r) {
        if (mi[r]) {
            const unsigned o = base + (r << 9) + tid;
            aA[r] = __ldcs(&adj4[o]);
            aB[r] = __ldcs(&adj4[o + 256]);
        }
    }

    const float4* sj4 = reinterpret_cast<const float4*>(g_sj);
    const int4*   mj4 = reinterpret_cast<const int4*>(mask);
    const float4 sjA = __ldg(&sj4[cbase]);
    const float4 sjB = __ldg(&sj4[cbase + 256]);
    const int4   mA  = __ldg(&mj4[cbase]);
    const int4   mB  = __ldg(&mj4[cbase + 256]);

#pragma unroll
    for (int r = 0; r < 4; ++r) {
        if (mi[r]) {
            const unsigned o  = base + (r << 9) + tid;
            const float    si = g_si[row0 + r];
            float4 out;
            out.x = sig_blend(si, sjA.x, mA.x, aA[r].x);
            out.y = sig_blend(si, sjA.y, mA.y, aA[r].y);
            out.z = sig_blend(si, sjA.z, mA.z, aA[r].z);
            out.w = sig_blend(si, sjA.w, mA.w, aA[r].w);
            __stcs(&out4[o], out);

            out.x = sig_blend(si, sjB.x, mB.x, aB[r].x);
            out.y = sig_blend(si, sjB.y, mB.y, aB[r].y);
            out.z = sig_blend(si, sjB.z, mB.z, aB[r].z);
            out.w = sig_blend(si, sjB.w, mB.w, aB[r].w);
            __stcs(&out4[o + 256], out);
        }
    }
}

// ---------------------------------------------------------------------------
// Launch
// Inputs (metadata order): 0:x [16,2048,256] f32, 1:adj [16,2048,2048] f32,
//                          2:mask [16,2048] i32, 3:W [1,512] f32, 4:b [1] f32
// Output: [16,2048,2048] f32
// ---------------------------------------------------------------------------
extern "C" void kernel_launch(void* const* d_in, const int* in_sizes, int n_in,
                              void* d_out, int out_size) {
    const float* x    = (const float*)d_in[0];
    const float4* adj = (const float4*)d_in[1];
    const int*   mask = (const int*)d_in[2];
    const float* W    = (const float*)d_in[3];
    const float* bias = (const float*)d_in[4];
    float4* out = (float4*)d_out;

    reset_kernel<<<1, 1>>>();
    mono_kernel<<<QUADS, 256>>>(x, adj, mask, W, bias, out);
}

// round 9
// speedup vs baseline: 1.3895x; 1.0424x over previous
#include <cuda_runtime.h>
#include <cuda_bf16.h>

// Problem shape (fixed by the dataset)
#define B_DIM 16
#define S_DIM 2048
#define D_DIM 256
#define ROWS  (B_DIM * S_DIM)          // 32768
#define P_ASEM 0.6f
#define Q_ASEM 0.4f
#define MASK_FILL 1e-9f

// Scratch for projected scores (no cudaMalloc allowed)
__device__ float g_si[ROWS];  // si + bias folded in
__device__ float g_sj[ROWS];

// ---------------------------------------------------------------------------
// Kernel 1: dual dot products, 4 rows per warp, MLP=8 (R6 version).
// ---------------------------------------------------------------------------
#define PROJ_RPW 4   // rows per warp

__global__ __launch_bounds__(256) void proj_kernel(const float* __restrict__ x,
                                                   const float* __restrict__ W,
                                                   const float* __restrict__ bias) {
    const int warp = blockIdx.x * (blockDim.x >> 5) + (threadIdx.x >> 5);
    const int lane = threadIdx.x & 31;
    const int row0 = warp * PROJ_RPW;

    const float4* Wi4 = reinterpret_cast<const float4*>(W);            // W[0:256]
    const float4* Wj4 = reinterpret_cast<const float4*>(W + D_DIM);    // W[256:512]

    // issue all x loads up front (8 independent LDG.128 per thread)
    float4 xv[PROJ_RPW][2];
#pragma unroll
    for (int r = 0; r < PROJ_RPW; ++r) {
        const float4* x4 = reinterpret_cast<const float4*>(x) +
                           (long)(row0 + r) * (D_DIM / 4);
        xv[r][0] = x4[lane];
        xv[r][1] = x4[lane + 32];
    }

    const float4 wi0 = __ldg(&Wi4[lane]);
    const float4 wi1 = __ldg(&Wi4[lane + 32]);
    const float4 wj0 = __ldg(&Wj4[lane]);
    const float4 wj1 = __ldg(&Wj4[lane + 32]);

    float si[PROJ_RPW], sj[PROJ_RPW];
#pragma unroll
    for (int r = 0; r < PROJ_RPW; ++r) {
        float a = 0.f, b2 = 0.f;
        a = fmaf(xv[r][0].x, wi0.x, a); a = fmaf(xv[r][0].y, wi0.y, a);
        a = fmaf(xv[r][0].z, wi0.z, a); a = fmaf(xv[r][0].w, wi0.w, a);
        a = fmaf(xv[r][1].x, wi1.x, a); a = fmaf(xv[r][1].y, wi1.y, a);
        a = fmaf(xv[r][1].z, wi1.z, a); a = fmaf(xv[r][1].w, wi1.w, a);
        b2 = fmaf(xv[r][0].x, wj0.x, b2); b2 = fmaf(xv[r][0].y, wj0.y, b2);
        b2 = fmaf(xv[r][0].z, wj0.z, b2); b2 = fmaf(xv[r][0].w, wj0.w, b2);
        b2 = fmaf(xv[r][1].x, wj1.x, b2); b2 = fmaf(xv[r][1].y, wj1.y, b2);
        b2 = fmaf(xv[r][1].z, wj1.z, b2); b2 = fmaf(xv[r][1].w, wj1.w, b2);
        si[r] = a; sj[r] = b2;
    }

#pragma unroll
    for (int off = 16; off > 0; off >>= 1) {
#pragma unroll
        for (int r = 0; r < PROJ_RPW; ++r) {
            si[r] += __shfl_down_sync(0xFFFFFFFFu, si[r], off);
            sj[r] += __shfl_down_sync(0xFFFFFFFFu, sj[r], off);
        }
    }
    if (lane == 0) {
        const float bv = __ldg(bias);
#pragma unroll
        for (int r = 0; r < PROJ_RPW; ++r) {
            g_si[row0 + r] = si[r] + bv;
            g_sj[row0 + r] = sj[r];
        }
    }
}

// ---------------------------------------------------------------------------
// Kernel 2: fused elementwise, 4 rows per block (same batch -> shared column
// vectors). Single change vs R6: masked-row FILL STORES ISSUE FIRST so the
// store stream starts draining while the adj loads are outstanding.
// ---------------------------------------------------------------------------
#define RPB 4   // rows per block

__device__ __forceinline__ float sig_blend(float si, float sjv, int m, float a) {
    float z = si + sjv;
    float s = __fdividef(1.f, 1.f + __expf(-z));
    return m ? fmaf(P_ASEM, s, Q_ASEM * a) : MASK_FILL;
}

__global__ __launch_bounds__(256) void fuse_kernel(const float4* __restrict__ adj4,
                                                   const int*    __restrict__ mask,
                                                   float4*       __restrict__ out4) {
    const unsigned tid   = threadIdx.x;
    const unsigned row0  = blockIdx.x * RPB;                 // rows row0..row0+3 (same batch)
    const unsigned base  = row0 << 9;                        // first float4 of the block
    const unsigned cbase = ((row0 >> 11) << 9) + tid;        // sj/mask col float4 index

    // per-row masks (uniform across block for each row)
    int mi[RPB];
#pragma unroll
    for (int r = 0; r < RPB; ++r) mi[r] = mask[row0 + r];

    // masked rows: fill stores FIRST (no data dependency, drain early)
    const float4 fill = make_float4(MASK_FILL, MASK_FILL, MASK_FILL, MASK_FILL);
#pragma unroll
    for (int r = 0; r < RPB; ++r) {
        if (!mi[r]) {
            const unsigned o = base + (r << 9) + tid;
            __stcs(&out4[o], fill);
            __stcs(&out4[o + 256], fill);
        }
    }

    // issue ALL adj loads for unmasked rows (predicated, independent)
    float4 aA[RPB], aB[RPB];
#pragma unroll
    for (int r = 0; r < RPB; ++r) {
        if (mi[r]) {
            const unsigned o = base + (r << 9) + tid;
            aA[r] = __ldcs(&adj4[o]);
            aB[r] = __ldcs(&adj4[o + 256]);
        }
    }

    // column vectors: shared by all RPB rows, loaded once
    const float4* sj4 = reinterpret_cast<const float4*>(g_sj);
    const int4*   mj4 = reinterpret_cast<const int4*>(mask);
    const float4 sjA = __ldg(&sj4[cbase]);
    const float4 sjB = __ldg(&sj4[cbase + 256]);
    const int4   mA  = __ldg(&mj4[cbase]);
    const int4   mB  = __ldg(&mj4[cbase + 256]);

#pragma unroll
    for (int r = 0; r < RPB; ++r) {
        if (mi[r]) {
            const unsigned o  = base + (r << 9) + tid;
            const float    si = g_si[row0 + r];
            float4 out;
            out.x = sig_blend(si, sjA.x, mA.x, aA[r].x);
            out.y = sig_blend(si, sjA.y, mA.y, aA[r].y);
            out.z = sig_blend(si, sjA.z, mA.z, aA[r].z);
            out.w = sig_blend(si, sjA.w, mA.w, aA[r].w);
            __stcs(&out4[o], out);

            out.x = sig_blend(si, sjB.x, mB.x, aB[r].x);
            out.y = sig_blend(si, sjB.y, mB.y, aB[r].y);
            out.z = sig_blend(si, sjB.z, mB.z, aB[r].z);
            out.w = sig_blend(si, sjB.w, mB.w, aB[r].w);
            __stcs(&out4[o + 256], out);
        }
    }
}

// ---------------------------------------------------------------------------
// Launch
// Inputs (metadata order): 0:x [16,2048,256] f32, 1:adj [16,2048,2048] f32,
//                          2:mask [16,2048] i32, 3:W [1,512] f32, 4:b [1] f32
// Output: [16,2048,2048] f32
// ---------------------------------------------------------------------------
extern "C" void kernel_launch(void* const* d_in, const int* in_sizes, int n_in,
                              void* d_out, int out_size) {
    const float* x    = (const float*)d_in[0];
    const float* adj  = (const float*)d_in[1];
    const int*   mask = (const int*)d_in[2];
    const float* W    = (const float*)d_in[3];
    const float* bias = (const float*)d_in[4];
    float* out = (float*)d_out;

    // Kernel 1: 4 rows/warp, 8 warps/block -> 32 rows/block -> 1024 blocks
    proj_kernel<<<ROWS / (PROJ_RPW * 8), 256>>>(x, W, bias);

    // Kernel 2: one block per 4 output rows -> 8192 blocks
    fuse_kernel<<<ROWS / RPB, 256>>>(reinterpret_cast<const float4*>(adj),
                                     mask,
                                     reinterpret_cast<float4*>(out));
}

// round 10
// speedup vs baseline: 1.4271x; 1.0271x over previous
#include <cuda_runtime.h>
#include <cuda_bf16.h>

// Problem shape (fixed by the dataset)
#define B_DIM 16
#define S_DIM 2048
#define D_DIM 256
#define ROWS  (B_DIM * S_DIM)          // 32768
#define P_ASEM 0.6f
#define Q_ASEM 0.4f
#define MASK_FILL 1e-9f

// Scratch for projected scores (no cudaMalloc allowed)
__device__ float g_si[ROWS];  // si + bias folded in
__device__ float g_sj[ROWS];

// ---------------------------------------------------------------------------
// Kernel 1: dual dot products, 4 rows per warp, MLP up to 8 — with masked-row
// skip: rows whose mask is 0 never have their projections consumed (the fuse
// select discards them), so we skip their x loads / FMAs / stores entirely.
// ---------------------------------------------------------------------------
#define PROJ_RPW 4   // rows per warp

__global__ __launch_bounds__(256) void proj_kernel(const float* __restrict__ x,
                                                   const int*   __restrict__ mask,
                                                   const float* __restrict__ W,
                                                   const float* __restrict__ bias) {
    const int warp = blockIdx.x * (blockDim.x >> 5) + (threadIdx.x >> 5);
    const int lane = threadIdx.x & 31;
    const int row0 = warp * PROJ_RPW;

    // row masks (warp-uniform per row)
    int mrow[PROJ_RPW];
#pragma unroll
    for (int r = 0; r < PROJ_RPW; ++r) mrow[r] = __ldg(&mask[row0 + r]);

    const float4* Wi4 = reinterpret_cast<const float4*>(W);            // W[0:256]
    const float4* Wj4 = reinterpret_cast<const float4*>(W + D_DIM);    // W[256:512]

    // issue x loads up front, only for live rows
    float4 xv[PROJ_RPW][2];
#pragma unroll
    for (int r = 0; r < PROJ_RPW; ++r) {
        if (mrow[r]) {
            const float4* x4 = reinterpret_cast<const float4*>(x) +
                               (long)(row0 + r) * (D_DIM / 4);
            xv[r][0] = x4[lane];
            xv[r][1] = x4[lane + 32];
        }
    }

    const float4 wi0 = __ldg(&Wi4[lane]);
    const float4 wi1 = __ldg(&Wi4[lane + 32]);
    const float4 wj0 = __ldg(&Wj4[lane]);
    const float4 wj1 = __ldg(&Wj4[lane + 32]);

    float si[PROJ_RPW], sj[PROJ_RPW];
#pragma unroll
    for (int r = 0; r < PROJ_RPW; ++r) {
        if (!mrow[r]) { si[r] = 0.f; sj[r] = 0.f; continue; }
        float a = 0.f, b2 = 0.f;
        a = fmaf(xv[r][0].x, wi0.x, a); a = fmaf(xv[r][0].y, wi0.y, a);
        a = fmaf(xv[r][0].z, wi0.z, a); a = fmaf(xv[r][0].w, wi0.w, a);
        a = fmaf(xv[r][1].x, wi1.x, a); a = fmaf(xv[r][1].y, wi1.y, a);
        a = fmaf(xv[r][1].z, wi1.z, a); a = fmaf(xv[r][1].w, wi1.w, a);
        b2 = fmaf(xv[r][0].x, wj0.x, b2); b2 = fmaf(xv[r][0].y, wj0.y, b2);
        b2 = fmaf(xv[r][0].z, wj0.z, b2); b2 = fmaf(xv[r][0].w, wj0.w, b2);
        b2 = fmaf(xv[r][1].x, wj1.x, b2); b2 = fmaf(xv[r][1].y, wj1.y, b2);
        b2 = fmaf(xv[r][1].z, wj1.z, b2); b2 = fmaf(xv[r][1].w, wj1.w, b2);
        si[r] = a; sj[r] = b2;
    }

#pragma unroll
    for (int off = 16; off > 0; off >>= 1) {
#pragma unroll
        for (int r = 0; r < PROJ_RPW; ++r) {
            if (mrow[r]) {
                si[r] += __shfl_down_sync(0xFFFFFFFFu, si[r], off);
                sj[r] += __shfl_down_sync(0xFFFFFFFFu, sj[r], off);
            }
        }
    }
    if (lane == 0) {
        const float bv = __ldg(bias);
#pragma unroll
        for (int r = 0; r < PROJ_RPW; ++r) {
            if (mrow[r]) {
                g_si[row0 + r] = si[r] + bv;
                g_sj[row0 + r] = sj[r];
            }
        }
    }
}

// ---------------------------------------------------------------------------
// Kernel 2: EXACT R6 fuse body (proven 60.7us) — do not reorder.
// 4 rows per block (same batch -> shared column vectors); adj loads for
// unmasked rows issued up front; masked rows write pure fill in-loop.
// ---------------------------------------------------------------------------
#define RPB 4   // rows per block

__device__ __forceinline__ float sig_blend(float si, float sjv, int m, float a) {
    float z = si + sjv;
    float s = __fdividef(1.f, 1.f + __expf(-z));
    return m ? fmaf(P_ASEM, s, Q_ASEM * a) : MASK_FILL;
}

__global__ __launch_bounds__(256) void fuse_kernel(const float4* __restrict__ adj4,
                                                   const int*    __restrict__ mask,
                                                   float4*       __restrict__ out4) {
    const unsigned tid   = threadIdx.x;
    const unsigned row0  = blockIdx.x * RPB;                 // rows row0..row0+3 (same batch)
    const unsigned base  = row0 << 9;                        // first float4 of the block
    const unsigned cbase = ((row0 >> 11) << 9) + tid;        // sj/mask col float4 index

    // per-row masks (uniform across block for each row)
    int mi[RPB];
#pragma unroll
    for (int r = 0; r < RPB; ++r) mi[r] = mask[row0 + r];

    // issue ALL adj loads for unmasked rows up front (predicated, independent)
    float4 aA[RPB], aB[RPB];
#pragma unroll
    for (int r = 0; r < RPB; ++r) {
        if (mi[r]) {
            const unsigned o = base + (r << 9) + tid;
            aA[r] = __ldcs(&adj4[o]);
            aB[r] = __ldcs(&adj4[o + 256]);
        }
    }

    // column vectors: shared by all RPB rows, loaded once
    const float4* sj4 = reinterpret_cast<const float4*>(g_sj);
    const int4*   mj4 = reinterpret_cast<const int4*>(mask);
    const float4 sjA = __ldg(&sj4[cbase]);
    const float4 sjB = __ldg(&sj4[cbase + 256]);
    const int4   mA  = __ldg(&mj4[cbase]);
    const int4   mB  = __ldg(&mj4[cbase + 256]);

#pragma unroll
    for (int r = 0; r < RPB; ++r) {
        const unsigned o = base + (r << 9) + tid;
        if (mi[r]) {
            const float si = g_si[row0 + r];
            float4 out;
            out.x = sig_blend(si, sjA.x, mA.x, aA[r].x);
            out.y = sig_blend(si, sjA.y, mA.y, aA[r].y);
            out.z = sig_blend(si, sjA.z, mA.z, aA[r].z);
            out.w = sig_blend(si, sjA.w, mA.w, aA[r].w);
            __stcs(&out4[o], out);

            out.x = sig_blend(si, sjB.x, mB.x, aB[r].x);
            out.y = sig_blend(si, sjB.y, mB.y, aB[r].y);
            out.z = sig_blend(si, sjB.z, mB.z, aB[r].z);
            out.w = sig_blend(si, sjB.w, mB.w, aB[r].w);
            __stcs(&out4[o + 256], out);
        } else {
            const float4 fill = make_float4(MASK_FILL, MASK_FILL, MASK_FILL, MASK_FILL);
            __stcs(&out4[o], fill);
            __stcs(&out4[o + 256], fill);
        }
    }
}

// ---------------------------------------------------------------------------
// Launch
// Inputs (metadata order): 0:x [16,2048,256] f32, 1:adj [16,2048,2048] f32,
//                          2:mask [16,2048] i32, 3:W [1,512] f32, 4:b [1] f32
// Output: [16,2048,2048] f32
// ---------------------------------------------------------------------------
extern "C" void kernel_launch(void* const* d_in, const int* in_sizes, int n_in,
                              void* d_out, int out_size) {
    const float* x    = (const float*)d_in[0];
    const float* adj  = (const float*)d_in[1];
    const int*   mask = (const int*)d_in[2];
    const float* W    = (const float*)d_in[3];
    const float* bias = (const float*)d_in[4];
    float* out = (float*)d_out;

    // Kernel 1: 4 rows/warp, 8 warps/block -> 32 rows/block -> 1024 blocks
    proj_kernel<<<ROWS / (PROJ_RPW * 8), 256>>>(x, mask, W, bias);

    // Kernel 2: one block per 4 output rows -> 8192 blocks
    fuse_kernel<<<ROWS / RPB, 256>>>(reinterpret_cast<const float4*>(adj),
                                     mask,
                                     reinterpret_cast<float4*>(out));
}